// round 1
// baseline (speedup 1.0000x reference)
#include <cuda_runtime.h>

// Problem constants: B=2, L=24, R=8, C=32, H=48, Wf=49
#define NB 2
#define NL 24
#define NR 8
#define NC 32
#define NH 48
#define NW 49

// Derived
#define RCW   12544      // R*C*Wf
#define HW    2352       // H*Wf
#define NINNER 602112    // R*C*H*Wf  (per (b,l) slab of u)
#define NINNER4 150528   // NINNER/4
#define ATOT  602112     // B*L*RCW
#define TOTCOMP4 7225344 // B*L*NINNER4  (float4 per output component)

// Scratch for precomputed decay rotation coefficients (4.8 MB)
__device__ float g_Ar[ATOT];
__device__ float g_Ai[ATOT];

// Kernel 1: A_r = exp(-nu*dt)*cos(theta*dt), A_i = exp(-nu*dt)*sin(theta*dt)
// One thread per (b,l,r,c,w). dt indexed by bl = i / RCW.
__global__ void compute_A_kernel(const float* __restrict__ nu,
                                 const float* __restrict__ th,
                                 const float* __restrict__ dt_seq) {
    int i = blockIdx.x * blockDim.x + threadIdx.x;
    if (i >= ATOT) return;
    int bl = i / RCW;                 // combined b*L + l, matches dt_seq flat layout
    float dt = __ldg(&dt_seq[bl]);
    float decay = expf(-nu[i] * dt);
    float s, c;
    sincosf(th[i] * dt, &s, &c);
    g_Ar[i] = decay * c;
    g_Ai[i] = decay * s;
}

// Kernel 2: sequential complex recurrence h_l = A_l*h_{l-1} + u_l over L=24,
// one thread per 4 adjacent channels (float4 u/out traffic).
__global__ void __launch_bounds__(256)
scan_kernel(const float4* __restrict__ ur4,
            const float4* __restrict__ ui4,
            float4* __restrict__ out4) {
    int t = blockIdx.x * blockDim.x + threadIdx.x;
    if (t >= NB * NINNER4) return;

    int b  = t / NINNER4;
    int c4 = t - b * NINNER4;     // float4 index within the (b,l) slab
    int c0 = c4 * 4;              // first scalar channel of this thread

    // Per-element A offsets within a (b,l) slab of A: rc*Wf + w
    int aoff0, aoff1, aoff2, aoff3;
    {
        int ce, rc, w;
        ce = c0 + 0; rc = ce / HW; w = ce % NW; aoff0 = rc * NW + w;
        ce = c0 + 1; rc = ce / HW; w = ce % NW; aoff1 = rc * NW + w;
        ce = c0 + 2; rc = ce / HW; w = ce % NW; aoff2 = rc * NW + w;
        ce = c0 + 3; rc = ce / HW; w = ce % NW; aoff3 = rc * NW + w;
    }

    int abase = b * (NL * RCW);           // A slab base for (b, l=0)
    int ubase = b * (NL * NINNER4) + c4;  // float4 index for (b, l=0)

    float hr0 = 0.f, hr1 = 0.f, hr2 = 0.f, hr3 = 0.f;
    float hi0 = 0.f, hi1 = 0.f, hi2 = 0.f, hi3 = 0.f;

    #pragma unroll
    for (int l = 0; l < NL; l++) {
        float4 u_r = __ldg(&ur4[ubase]);
        float4 u_i = __ldg(&ui4[ubase]);

        float ar0 = g_Ar[abase + aoff0], ai0 = g_Ai[abase + aoff0];
        float ar1 = g_Ar[abase + aoff1], ai1 = g_Ai[abase + aoff1];
        float ar2 = g_Ar[abase + aoff2], ai2 = g_Ai[abase + aoff2];
        float ar3 = g_Ar[abase + aoff3], ai3 = g_Ai[abase + aoff3];

        float nr, ni;
        nr = ar0 * hr0 - ai0 * hi0 + u_r.x;
        ni = ar0 * hi0 + ai0 * hr0 + u_i.x;
        hr0 = nr; hi0 = ni;
        nr = ar1 * hr1 - ai1 * hi1 + u_r.y;
        ni = ar1 * hi1 + ai1 * hr1 + u_i.y;
        hr1 = nr; hi1 = ni;
        nr = ar2 * hr2 - ai2 * hi2 + u_r.z;
        ni = ar2 * hi2 + ai2 * hr2 + u_i.z;
        hr2 = nr; hi2 = ni;
        nr = ar3 * hr3 - ai3 * hi3 + u_r.w;
        ni = ar3 * hi3 + ai3 * hr3 + u_i.w;
        hr3 = nr; hi3 = ni;

        out4[ubase]            = make_float4(hr0, hr1, hr2, hr3);
        out4[TOTCOMP4 + ubase] = make_float4(hi0, hi1, hi2, hi3);

        ubase += NINNER4;
        abase += RCW;
    }
}

extern "C" void kernel_launch(void* const* d_in, const int* in_sizes, int n_in,
                              void* d_out, int out_size) {
    // metadata order: nu_rate, theta_rate, dt_seq, u_real, u_imag
    const float* nu     = (const float*)d_in[0];
    const float* th     = (const float*)d_in[1];
    const float* dt_seq = (const float*)d_in[2];
    const float* u_real = (const float*)d_in[3];
    const float* u_imag = (const float*)d_in[4];
    float* out = (float*)d_out;

    {
        int n = ATOT;
        int threads = 256;
        int blocks = (n + threads - 1) / threads;
        compute_A_kernel<<<blocks, threads>>>(nu, th, dt_seq);
    }
    {
        int n = NB * NINNER4;   // 301,056 threads
        int threads = 256;
        int blocks = (n + threads - 1) / threads;
        scan_kernel<<<blocks, threads>>>((const float4*)u_real,
                                         (const float4*)u_imag,
                                         (float4*)out);
    }
}

// round 3
// speedup vs baseline: 1.0767x; 1.0767x over previous
#include <cuda_runtime.h>

// Problem constants: B=2, L=24, R=8, C=32, H=48, Wf=49
#define NB 2
#define NL 24
#define NR 8
#define NC 32
#define NH 48
#define NW 49

// Derived
#define RCW   12544      // R*C*Wf
#define HW    2352       // H*Wf
#define NINNER 602112    // R*C*H*Wf  (per (b,l) slab of u)
#define NINNER4 150528   // NINNER/4
#define ATOT  602112     // B*L*RCW
#define TOTCOMP4 7225344 // B*L*NINNER4  (float4 per output component)

// Scratch: interleaved (A_r, A_i) decay-rotation coefficients (4.8 MB)
__device__ float2 g_A[ATOT];

// Kernel 1: A = exp(-nu*dt) * (cos(th*dt), sin(th*dt)), fast-math MUFU path.
// Args are small (|th*dt| < ~6), well inside __sincosf accuracy range.
__global__ void compute_A_kernel(const float* __restrict__ nu,
                                 const float* __restrict__ th,
                                 const float* __restrict__ dt_seq) {
    int i = blockIdx.x * blockDim.x + threadIdx.x;
    if (i >= ATOT) return;
    int bl = i / RCW;                 // combined b*L + l, matches dt_seq flat layout
    float dt = __ldg(&dt_seq[bl]);
    float decay = __expf(-nu[i] * dt);
    float s, c;
    __sincosf(th[i] * dt, &s, &c);
    g_A[i] = make_float2(decay * c, decay * s);
}

// Kernel 2: sequential complex recurrence h_l = A_l*h_{l-1} + u_l over L=24,
// one thread per 4 adjacent channels (float4 u/out traffic), streaming hints.
__global__ void __launch_bounds__(128, 9)
scan_kernel(const float4* __restrict__ ur4,
            const float4* __restrict__ ui4,
            float4* __restrict__ out4) {
    int t = blockIdx.x * blockDim.x + threadIdx.x;
    if (t >= NB * NINNER4) return;

    int b  = t / NINNER4;
    int c4 = t - b * NINNER4;     // float4 index within the (b,l) slab
    int c0 = c4 * 4;              // first scalar channel of this thread

    // Per-element A offsets within a (b,l) slab of A: rc*Wf + w
    int aoff0, aoff1, aoff2, aoff3;
    {
        int ce, rc, w;
        ce = c0 + 0; rc = ce / HW; w = ce % NW; aoff0 = rc * NW + w;
        ce = c0 + 1; rc = ce / HW; w = ce % NW; aoff1 = rc * NW + w;
        ce = c0 + 2; rc = ce / HW; w = ce % NW; aoff2 = rc * NW + w;
        ce = c0 + 3; rc = ce / HW; w = ce % NW; aoff3 = rc * NW + w;
    }

    int abase = b * (NL * RCW);           // A slab base for (b, l=0)
    int ubase = b * (NL * NINNER4) + c4;  // float4 index for (b, l=0)

    float hr0 = 0.f, hr1 = 0.f, hr2 = 0.f, hr3 = 0.f;
    float hi0 = 0.f, hi1 = 0.f, hi2 = 0.f, hi3 = 0.f;

    #pragma unroll
    for (int l = 0; l < NL; l++) {
        float4 u_r = __ldcs(&ur4[ubase]);
        float4 u_i = __ldcs(&ui4[ubase]);

        float2 a0 = g_A[abase + aoff0];
        float2 a1 = g_A[abase + aoff1];
        float2 a2 = g_A[abase + aoff2];
        float2 a3 = g_A[abase + aoff3];

        float nr, ni;
        nr = a0.x * hr0 - a0.y * hi0 + u_r.x;
        ni = a0.x * hi0 + a0.y * hr0 + u_i.x;
        hr0 = nr; hi0 = ni;
        nr = a1.x * hr1 - a1.y * hi1 + u_r.y;
        ni = a1.x * hi1 + a1.y * hr1 + u_i.y;
        hr1 = nr; hi1 = ni;
        nr = a2.x * hr2 - a2.y * hi2 + u_r.z;
        ni = a2.x * hi2 + a2.y * hr2 + u_i.z;
        hr2 = nr; hi2 = ni;
        nr = a3.x * hr3 - a3.y * hi3 + u_r.w;
        ni = a3.x * hi3 + a3.y * hr3 + u_i.w;
        hr3 = nr; hi3 = ni;

        __stcs(&out4[ubase],            make_float4(hr0, hr1, hr2, hr3));
        __stcs(&out4[TOTCOMP4 + ubase], make_float4(hi0, hi1, hi2, hi3));

        ubase += NINNER4;
        abase += RCW;
    }
}

extern "C" void kernel_launch(void* const* d_in, const int* in_sizes, int n_in,
                              void* d_out, int out_size) {
    // metadata order: nu_rate, theta_rate, dt_seq, u_real, u_imag
    const float* nu     = (const float*)d_in[0];
    const float* th     = (const float*)d_in[1];
    const float* dt_seq = (const float*)d_in[2];
    const float* u_real = (const float*)d_in[3];
    const float* u_imag = (const float*)d_in[4];
    float* out = (float*)d_out;

    {
        int n = ATOT;
        int threads = 256;
        int blocks = (n + threads - 1) / threads;
        compute_A_kernel<<<blocks, threads>>>(nu, th, dt_seq);
    }
    {
        int n = NB * NINNER4;   // 301,056 threads
        int threads = 128;
        int blocks = (n + threads - 1) / threads;   // 2352 blocks
        scan_kernel<<<blocks, threads>>>((const float4*)u_real,
                                         (const float4*)u_imag,
                                         (float4*)out);
    }
}